// round 13
// baseline (speedup 1.0000x reference)
#include <cuda_runtime.h>
#include <cuda_bf16.h>
#include <cstdint>

#define THREADS 256
#define ATTNW_SHIFT 20.0f
#define INV_SQRT_D  0.17677669529663687f
#define SQRT3       1.7320508075688772f
#define SQRT32      5.656854249492381f
#define L2E         1.4426950408889634f

// word(=float)-index smem layout
#define WG2H  0        // 128*20
#define WG2L  2560
#define WWTH  5120     // 384*20
#define WWTL  12800
#define WPHH  20480    // 128*36 (Q words 0-15, K words 16-31)
#define WPHL  25088
#define WCTH  29696    // 32*68
#define WCTL  31872
#define F_H2X 34048
#define F_H2Y 34176
#define F_H2Z 34304
#define F_SW  34432
#define F_SWM 34560
#define F_BH  34688
#define F_WEQ 34720
// init-only raw-weight scratch:
#define F_RQK 34752    // 8192 floats
#define F_RWV 42944    // 4096
#define F_RWH 47040    // 4096
#define SMEM_BYTES 204544

static __device__ __forceinline__ uint32_t smem_u32(const void* p) {
    uint32_t a;
    asm("{ .reg .u64 t; cvta.to.shared.u64 t, %1; cvt.u32.u64 %0, t; }" : "=r"(a) : "l"(p));
    return a;
}
static __device__ __forceinline__ uint32_t packb(float e0, float e1) {
    uint32_t r;
    asm("cvt.rn.bf16x2.f32 %0, %1, %2;" : "=r"(r) : "f"(e1), "f"(e0));
    return r;
}
static __device__ __forceinline__ void pack_hl(float v0, float v1,
                                               uint32_t& h, uint32_t& l) {
    h = packb(v0, v1);
    float h0 = __uint_as_float(h << 16);
    float h1 = __uint_as_float(h & 0xFFFF0000u);
    l = packb(v0 - h0, v1 - h1);
}
static __device__ __forceinline__ float ex2a(float x) {
    float r; asm("ex2.approx.f32 %0, %1;" : "=f"(r) : "f"(x)); return r;
}
static __device__ __forceinline__ void mma16(float* d, uint32_t a0, uint32_t a1,
                                             uint32_t a2, uint32_t a3,
                                             uint32_t b0, uint32_t b1) {
    asm volatile("mma.sync.aligned.m16n8k16.row.col.f32.bf16.bf16.f32 "
                 "{%0,%1,%2,%3}, {%4,%5,%6,%7}, {%8,%9}, {%0,%1,%2,%3};"
                 : "+f"(d[0]), "+f"(d[1]), "+f"(d[2]), "+f"(d[3])
                 : "r"(a0), "r"(a1), "r"(a2), "r"(a3), "r"(b0), "r"(b1));
}
static __device__ __forceinline__ void mma3(float* d, const uint32_t* ah,
                                            const uint32_t* al,
                                            uint32_t bh0, uint32_t bh1,
                                            uint32_t bl0, uint32_t bl1) {
    mma16(d, ah[0], ah[1], ah[2], ah[3], bh0, bh1);
    mma16(d, al[0], al[1], al[2], al[3], bh0, bh1);
    mma16(d, ah[0], ah[1], ah[2], ah[3], bl0, bl1);
}
// build A-frag (hi/lo) from two adjacent n8 accumulator tiles scaled per-row
static __device__ __forceinline__ void afrag_from_acc(const float* acc0, const float* acc1,
                                                      float s0, float s1,
                                                      uint32_t* ah, uint32_t* al) {
    pack_hl(acc0[0] * s0, acc0[1] * s0, ah[0], al[0]);
    pack_hl(acc0[2] * s1, acc0[3] * s1, ah[1], al[1]);
    pack_hl(acc1[0] * s0, acc1[1] * s0, ah[2], al[2]);
    pack_hl(acc1[2] * s1, acc1[3] * s1, ah[3], al[3]);
}
#define LDSM4(r, ba) \
    asm volatile("ldmatrix.sync.aligned.m8n8.x4.shared.b16 {%0,%1,%2,%3}, [%4];" \
                 : "=r"((r)[0]), "=r"((r)[1]), "=r"((r)[2]), "=r"((r)[3]) : "r"(ba))
#define STSM4(ba, r0, r1, r2, r3) \
    asm volatile("stmatrix.sync.aligned.m8n8.x4.shared.b16 [%0], {%1,%2,%3,%4};" \
                 :: "r"(ba), "r"(r0), "r"(r1), "r"(r2), "r"(r3))
#define STSM2T(ba, r0, r1) \
    asm volatile("stmatrix.sync.aligned.m8n8.x2.trans.shared.b16 [%0], {%1,%2};" \
                 :: "r"(ba), "r"(r0), "r"(r1))

__global__ void __launch_bounds__(THREADS, 1)
rep_bf16_kernel(const float* __restrict__ g2, const float* __restrict__ h2,
                const float* __restrict__ sw, const float* __restrict__ wqk,
                const float* __restrict__ wv, const float* __restrict__ wh,
                const float* __restrict__ bh, const float* __restrict__ weq,
                const int* __restrict__ mask, float* __restrict__ outg,
                float* __restrict__ outh)
{
    extern __shared__ __align__(16) float smf[];
    uint32_t* smu = (uint32_t*)smf;
    const uint32_t sb = smem_u32(smf);
    const int tid = threadIdx.x, w = tid >> 5, lane = tid & 31;
    const int g = lane >> 2, t = lane & 3;
    const int m0 = w * 16;
    const int loc = blockIdx.x;
    const int r8 = lane & 7, s01 = (lane >> 3) & 1, s2 = lane >> 4;

    const float* g2l = g2 + (size_t)loc * 128 * 32;
    const float* h2l = h2 + (size_t)loc * 128 * 3;
    const float* swl = sw + (size_t)loc * 128;
    const int*   ml  = mask + (size_t)loc * 128;

    // ---- stage raw weights ----
    {
        const float4* s1 = (const float4*)wqk;
        float4* d1 = (float4*)(smf + F_RQK);
        #pragma unroll
        for (int i = 0; i < 8; ++i) d1[tid + i * 256] = s1[tid + i * 256];
        const float4* s2p = (const float4*)wv;
        float4* d2 = (float4*)(smf + F_RWV);
        #pragma unroll
        for (int i = 0; i < 4; ++i) d2[tid + i * 256] = s2p[tid + i * 256];
        const float4* s3 = (const float4*)wh;
        float4* d3 = (float4*)(smf + F_RWH);
        #pragma unroll
        for (int i = 0; i < 4; ++i) d3[tid + i * 256] = s3[tid + i * 256];
    }
    // ---- g2 -> bf16 hi/lo (thread = half row) ----
    {
        int r = tid >> 1, hf = tid & 1;
        const float* src = g2l + (size_t)r * 32 + hf * 16;
        float e[16];
        #pragma unroll
        for (int i = 0; i < 4; ++i) {
            float4 v = ((const float4*)src)[i];
            e[4*i] = v.x; e[4*i+1] = v.y; e[4*i+2] = v.z; e[4*i+3] = v.w;
        }
        #pragma unroll
        for (int j = 0; j < 8; ++j) {
            uint32_t hu, lu;
            pack_hl(e[2*j], e[2*j+1], hu, lu);
            smu[WG2H + r * 20 + hf * 8 + j] = hu;
            smu[WG2L + r * 20 + hf * 8 + j] = lu;
        }
    }
    if (tid < 128) {
        float a = h2l[tid * 3], b = h2l[tid * 3 + 1], c = h2l[tid * 3 + 2];
        float sv = swl[tid];
        smf[F_H2X + tid] = a; smf[F_H2Y + tid] = b; smf[F_H2Z + tid] = c;
        smf[F_SW + tid] = sv;
        smf[F_SWM + tid] = ml[tid] ? sv : 0.0f;
    }
    if (tid < 32) smf[F_BH + tid] = bh[tid];
    if (tid < 4)  smf[F_WEQ + tid] = weq[tid];
    __syncthreads();

    // ---- WallT Q/K rows ----
    #pragma unroll 4
    for (int i = tid; i < 4096; i += THREADS) {
        int rqk = i >> 4, j = i & 15;
        int hh = rqk >> 6, r = rqk & 63;
        int c = hh * 96 + r;
        int src = (r < 32) ? r * 8 + hh : (r - 32) * 8 + 4 + hh;
        float v0 = smf[F_RQK + (2 * j) * 256 + src];
        float v1 = smf[F_RQK + (2 * j + 1) * 256 + src];
        uint32_t hu, lu;
        pack_hl(v0, v1, hu, lu);
        smu[WWTH + c * 20 + j] = hu;
        smu[WWTL + c * 20 + j] = lu;
    }
    // ---- WallT C rows: wc = wv @ wh folded per head ----
    if (tid < 128) {
        int hh = tid >> 5, m = tid & 31;
        float whcol[32];
        #pragma unroll 8
        for (int gg = 0; gg < 32; ++gg)
            whcol[gg] = smf[F_RWH + (gg * 4 + hh) * 32 + m];
        float acc[32];
        #pragma unroll 1
        for (int k = 0; k < 32; ++k) {
            const float* wvr = smf + F_RWV + k * 128 + hh;
            float s = 0.f;
            #pragma unroll
            for (int gg = 0; gg < 32; ++gg) s = fmaf(wvr[gg * 4], whcol[gg], s);
            acc[k] = s;
        }
        int c = hh * 96 + 64 + m;
        #pragma unroll
        for (int j = 0; j < 16; ++j) {
            uint32_t hu, lu;
            pack_hl(acc[2 * j], acc[2 * j + 1], hu, lu);
            smu[WWTH + c * 20 + j] = hu;
            smu[WWTL + c * 20 + j] = lu;
        }
    }
    __syncthreads();

    // ---- persistent state ----
    float oacc[4][4];
    #pragma unroll
    for (int a = 0; a < 4; ++a)
        #pragma unroll
        for (int b = 0; b < 4; ++b) oacc[a][b] = 0.f;
    float och[2][3] = {};
    float rswm[2], rh2I[2][3], rwL[2];
    #pragma unroll
    for (int mt2 = 0; mt2 < 2; ++mt2) {
        int row = m0 + g + mt2 * 8;
        rh2I[mt2][0] = smf[F_H2X + row] * INV_SQRT_D;
        rh2I[mt2][1] = smf[F_H2Y + row] * INV_SQRT_D;
        rh2I[mt2][2] = smf[F_H2Z + row] * INV_SQRT_D;
        rwL[mt2] = smf[F_SW + row] * L2E;
        rswm[mt2] = smf[F_SWM + row];
    }

    // lane-address bases (byte addrs)
    const int arow = m0 + r8 + s01 * 8;
    const uint32_t aG2h = sb + 4 * (WG2H + arow * 20 + s2 * 4);
    const uint32_t aG2l = sb + 4 * (WG2L + arow * 20 + s2 * 4);
    const uint32_t aPHh = sb + 4 * (WPHH + arow * 36 + s2 * 4);
    const uint32_t aPHl = sb + 4 * (WPHL + arow * 36 + s2 * 4);
    const uint32_t stPH = aPHh;
    const uint32_t stCT = sb + 4 * (WCTH + (lane & 7) * 68 + w * 8 + ((lane >> 3) & 1) * 4);
    const float C50 = -50.0f * L2E;

    #pragma unroll 1
    for (int h = 0; h < 4; ++h) {
        // ======== GEMM_P: Q(nt0-3)+K(nt4-7) -> Ph, C(nt8-11) -> Ct ========
        float pacc[12][4];
        #pragma unroll
        for (int a = 0; a < 12; ++a)
            #pragma unroll
            for (int b = 0; b < 4; ++b) pacc[a][b] = 0.f;
        #pragma unroll
        for (int kk = 0; kk < 2; ++kk) {
            uint32_t ah[4], al[4];
            LDSM4(ah, aG2h + 32 * kk);
            LDSM4(al, aG2l + 32 * kk);
            #pragma unroll
            for (int ntp = 0; ntp < 6; ++ntp) {
                int n = h * 96 + ntp * 16 + r8 + s2 * 8;
                uint32_t bb = sb + 4 * (WWTH + n * 20 + kk * 8 + s01 * 4);
                uint32_t bhr[4], blr[4];
                LDSM4(bhr, bb);
                LDSM4(blr, bb + 4 * (WWTL - WWTH));
                mma3(pacc[2*ntp],   ah, al, bhr[0], bhr[1], blr[0], blr[1]);
                mma3(pacc[2*ntp+1], ah, al, bhr[2], bhr[3], blr[2], blr[3]);
            }
        }
        // store Q,K -> Ph via stmatrix.x4 (hi/lo)
        #pragma unroll
        for (int ntp = 0; ntp < 4; ++ntp) {
            uint32_t h0, l0, h1, l1, h2r, l2, h3, l3;
            pack_hl(pacc[2*ntp][0],   pacc[2*ntp][1],   h0, l0);
            pack_hl(pacc[2*ntp][2],   pacc[2*ntp][3],   h1, l1);
            pack_hl(pacc[2*ntp+1][0], pacc[2*ntp+1][1], h2r, l2);
            pack_hl(pacc[2*ntp+1][2], pacc[2*ntp+1][3], h3, l3);
            STSM4(stPH + 32 * ntp, h0, h1, h2r, h3);
            STSM4(stPH + 32 * ntp + 4 * (WPHL - WPHH), l0, l1, l2, l3);
        }
        // store C transposed -> Ct via stmatrix.x2.trans (hi/lo)
        #pragma unroll
        for (int nt = 8; nt < 12; ++nt) {
            int j0 = (nt - 8) * 8;
            uint32_t h0, l0, h1, l1;
            pack_hl(pacc[nt][0], pacc[nt][1], h0, l0);
            pack_hl(pacc[nt][2], pacc[nt][3], h1, l1);
            uint32_t ba = stCT + 4 * (j0 * 68);
            STSM2T(ba, h0, h1);
            STSM2T(ba + 4 * (WCTL - WCTH), l0, l1);
        }
        __syncthreads();

        // ======== GEMM_S: Q,K from Ph ========
        float sacc[16][4];
        #pragma unroll
        for (int a = 0; a < 16; ++a)
            #pragma unroll
            for (int b = 0; b < 4; ++b) sacc[a][b] = 0.f;
        #pragma unroll
        for (int kk = 0; kk < 2; ++kk) {
            uint32_t ah[4], al[4];
            LDSM4(ah, aPHh + 32 * kk);
            LDSM4(al, aPHl + 32 * kk);
            #pragma unroll
            for (int ntp = 0; ntp < 8; ++ntp) {
                int n = ntp * 16 + r8 + s2 * 8;
                uint32_t bb = sb + 4 * (WPHH + n * 36 + 16 + kk * 8 + s01 * 4);
                uint32_t bhr[4], blr[4];
                LDSM4(bhr, bb);
                LDSM4(blr, bb + 4 * (WPHL - WPHH));
                mma3(sacc[2*ntp],   ah, al, bhr[0], bhr[1], blr[0], blr[1]);
                mma3(sacc[2*ntp+1], ah, al, bhr[2], bhr[3], blr[2], blr[3]);
            }
        }

        // ======== single-pass softmax ========
        float ssum[2] = {0.f, 0.f}, ochp[2][3] = {};
        #pragma unroll
        for (int nt = 0; nt < 16; ++nt) {
            int c0 = nt * 8 + 2 * t;
            float2 hx = *(float2*)(smf + F_H2X + c0);
            float2 hy = *(float2*)(smf + F_H2Y + c0);
            float2 hz = *(float2*)(smf + F_H2Z + c0);
            float2 hw = *(float2*)(smf + F_SW + c0);
            float2 hm = *(float2*)(smf + F_SWM + c0);
            #pragma unroll
            for (int b = 0; b < 2; ++b) {
                float cx = b ? hx.y : hx.x, cy = b ? hy.y : hy.x;
                float cz = b ? hz.y : hz.x, cw = b ? hw.y : hw.x;
                float cm = b ? hm.y : hm.x;
                #pragma unroll
                for (int mt2 = 0; mt2 < 2; ++mt2) {
                    float dot = sacc[nt][mt2 * 2 + b];
                    float h2dI = fmaf(rh2I[mt2][0], cx,
                               fmaf(rh2I[mt2][1], cy, rh2I[mt2][2] * cz));
                    float t1 = fmaf(dot, h2dI, ATTNW_SHIFT);
                    float e = ex2a(fmaf(t1, cw * rwL[mt2], C50));
                    ssum[mt2] += e;
                    float ap = (e * cm) * h2dI;
                    sacc[nt][mt2 * 2 + b] = ap;
                    ochp[mt2][0] = fmaf(ap, cx, ochp[mt2][0]);
                    ochp[mt2][1] = fmaf(ap, cy, ochp[mt2][1]);
                    ochp[mt2][2] = fmaf(ap, cz, ochp[mt2][2]);
                }
            }
        }
        float rowscale[2];
        float wqh = smf[F_WEQ + h];
        #pragma unroll
        for (int mt2 = 0; mt2 < 2; ++mt2) {
            float s = ssum[mt2];
            s += __shfl_xor_sync(0xffffffffu, s, 1);
            s += __shfl_xor_sync(0xffffffffu, s, 2);
            rowscale[mt2] = rswm[mt2] * SQRT32 / (fmaxf(s, 1e-30f) * SQRT3);
            float f = wqh * rowscale[mt2];
            och[mt2][0] = fmaf(f, ochp[mt2][0], och[mt2][0]);
            och[mt2][1] = fmaf(f, ochp[mt2][1], och[mt2][1]);
            och[mt2][2] = fmaf(f, ochp[mt2][2], och[mt2][2]);
        }

        // ======== GEMM_O: A = A' from registers; B = Ct from smem ========
        #pragma unroll 2
        for (int kk = 0; kk < 8; ++kk) {
            uint32_t ah[4], al[4];
            afrag_from_acc(sacc[2*kk], sacc[2*kk+1], rowscale[0], rowscale[1], ah, al);
            #pragma unroll
            for (int ntp = 0; ntp < 2; ++ntp) {
                int n = ntp * 16 + r8 + s2 * 8;
                uint32_t bb = sb + 4 * (WCTH + n * 68 + kk * 8 + s01 * 4);
                uint32_t bhr[4], blr[4];
                LDSM4(bhr, bb);
                LDSM4(blr, bb + 4 * (WCTL - WCTH));
                mma3(oacc[2*ntp],   ah, al, bhr[0], bhr[1], blr[0], blr[1]);
                mma3(oacc[2*ntp+1], ah, al, bhr[2], bhr[3], blr[2], blr[3]);
            }
        }
        __syncthreads();   // Ph/Ct reused next head
    }

    // ---- outputs ----
    #pragma unroll
    for (int hb = 0; hb < 2; ++hb) {
        int row = m0 + g + hb * 8;
        float* go = outg + ((size_t)loc * 128 + row) * 32;
        #pragma unroll
        for (int nt = 0; nt < 4; ++nt) {
            int col = nt * 8 + 2 * t;
            float2 v = make_float2(oacc[nt][hb * 2] + smf[F_BH + col],
                                   oacc[nt][hb * 2 + 1] + smf[F_BH + col + 1]);
            *(float2*)(go + col) = v;
        }
    }
    if (outh) {
        #pragma unroll
        for (int mt2 = 0; mt2 < 2; ++mt2) {
            #pragma unroll
            for (int c = 0; c < 3; ++c) {
                och[mt2][c] += __shfl_xor_sync(0xffffffffu, och[mt2][c], 1);
                och[mt2][c] += __shfl_xor_sync(0xffffffffu, och[mt2][c], 2);
            }
            if (t == 0) {
                int row = m0 + g + mt2 * 8;
                float* ho = outh + ((size_t)loc * 128 + row) * 3;
                ho[0] = och[mt2][0]; ho[1] = och[mt2][1]; ho[2] = och[mt2][2];
            }
        }
    }
}

extern "C" void kernel_launch(void* const* d_in, const int* in_sizes, int n_in,
                              void* d_out, int out_size) {
    const float* g2  = (const float*)d_in[0];
    const float* h2  = (const float*)d_in[1];
    const float* sw  = (const float*)d_in[2];
    const float* wqk = (const float*)d_in[3];
    const float* wv  = (const float*)d_in[4];
    const float* wh  = (const float*)d_in[5];
    const float* bh  = (const float*)d_in[6];
    const float* weq = (const float*)d_in[7];
    const int*   msk = (const int*)d_in[8];

    int nloc = in_sizes[2] / 128;
    float* outg = (float*)d_out;
    size_t gsz = (size_t)nloc * 128 * 32;
    float* outh = ((size_t)out_size >= gsz + (size_t)nloc * 128 * 3) ? outg + gsz : nullptr;

    cudaFuncSetAttribute(rep_bf16_kernel, cudaFuncAttributeMaxDynamicSharedMemorySize, SMEM_BYTES);
    rep_bf16_kernel<<<nloc, THREADS, SMEM_BYTES>>>(g2, h2, sw, wqk, wv, wh, bh, weq, msk, outg, outh);
}

// round 14
// speedup vs baseline: 1.2360x; 1.2360x over previous
#include <cuda_runtime.h>
#include <cuda_bf16.h>
#include <cstdint>

#define THREADS 256
#define ATTNW_SHIFT 20.0f
#define INV_SQRT_D  0.17677669529663687f
#define SQRT3       1.7320508075688772f
#define SQRT32      5.656854249492381f
#define L2E         1.4426950408889634f

// word(=float)-index smem layout
#define WG2H  0        // 128*20
#define WG2L  2560
#define WWTH  5120     // 384*20 (reused as RBUF at the end)
#define WWTL  12800
#define WPHH  20480    // 128*36 (Q words 0-15, K words 16-31)
#define WPHL  25088
#define WCTH  29696    // 40*68  (rows 0-31 C^T, 32-34 h2*weq, 35-39 zero)
#define WCTL  32416
#define WAPH  35136    // 128*68 A'
#define WAPL  43840
#define F_H2SW4 52544  // float4[128]: (h2x,h2y,h2z, mask? sw : -sw)
#define F_BH  53056
#define F_WEQ 53088
#define F_PART 53120   // 128*2 row-sum partials
#define SMEM_BYTES 213504
// init-only raw-weight scratch overlays WAP region:
#define F_RQK 35136
#define F_RWV 43328
#define F_RWH 47424
#define RBUF  WWTH
#define OFFPH 18432
#define OFFCT 10880
#define OFFAP 34816

static __device__ __forceinline__ uint32_t smem_u32(const void* p) {
    uint32_t a;
    asm("{ .reg .u64 t; cvta.to.shared.u64 t, %1; cvt.u32.u64 %0, t; }" : "=r"(a) : "l"(p));
    return a;
}
static __device__ __forceinline__ uint32_t packb(float e0, float e1) {
    uint32_t r;
    asm("cvt.rn.bf16x2.f32 %0, %1, %2;" : "=r"(r) : "f"(e1), "f"(e0));
    return r;
}
static __device__ __forceinline__ void pack_hl(float v0, float v1,
                                               uint32_t& h, uint32_t& l) {
    h = packb(v0, v1);
    float h0 = __uint_as_float(h << 16);
    float h1 = __uint_as_float(h & 0xFFFF0000u);
    l = packb(v0 - h0, v1 - h1);
}
static __device__ __forceinline__ float ex2a(float x) {
    float r; asm("ex2.approx.f32 %0, %1;" : "=f"(r) : "f"(x)); return r;
}
static __device__ __forceinline__ void mma16(float* d, uint32_t a0, uint32_t a1,
                                             uint32_t a2, uint32_t a3,
                                             uint32_t b0, uint32_t b1) {
    asm volatile("mma.sync.aligned.m16n8k16.row.col.f32.bf16.bf16.f32 "
                 "{%0,%1,%2,%3}, {%4,%5,%6,%7}, {%8,%9}, {%0,%1,%2,%3};"
                 : "+f"(d[0]), "+f"(d[1]), "+f"(d[2]), "+f"(d[3])
                 : "r"(a0), "r"(a1), "r"(a2), "r"(a3), "r"(b0), "r"(b1));
}
static __device__ __forceinline__ void mma3(float* d, const uint32_t* ah,
                                            const uint32_t* al,
                                            uint32_t bh0, uint32_t bh1,
                                            uint32_t bl0, uint32_t bl1) {
    mma16(d, ah[0], ah[1], ah[2], ah[3], bh0, bh1);
    mma16(d, al[0], al[1], al[2], al[3], bh0, bh1);
    mma16(d, ah[0], ah[1], ah[2], ah[3], bl0, bl1);
}
#define LDSM4(r, ba) \
    asm volatile("ldmatrix.sync.aligned.m8n8.x4.shared.b16 {%0,%1,%2,%3}, [%4];" \
                 : "=r"((r)[0]), "=r"((r)[1]), "=r"((r)[2]), "=r"((r)[3]) : "r"(ba))
#define LDSM2(r, ba) \
    asm volatile("ldmatrix.sync.aligned.m8n8.x2.shared.b16 {%0,%1}, [%2];" \
                 : "=r"((r)[0]), "=r"((r)[1]) : "r"(ba))
#define STSM4(ba, r0, r1, r2, r3) \
    asm volatile("stmatrix.sync.aligned.m8n8.x4.shared.b16 [%0], {%1,%2,%3,%4};" \
                 :: "r"(ba), "r"(r0), "r"(r1), "r"(r2), "r"(r3))
#define STSM2T(ba, r0, r1) \
    asm volatile("stmatrix.sync.aligned.m8n8.x2.trans.shared.b16 [%0], {%1,%2};" \
                 :: "r"(ba), "r"(r0), "r"(r1))

__global__ void __launch_bounds__(THREADS, 1)
rep_bf16_kernel(const float* __restrict__ g2, const float* __restrict__ h2,
                const float* __restrict__ sw, const float* __restrict__ wqk,
                const float* __restrict__ wv, const float* __restrict__ wh,
                const float* __restrict__ bh, const float* __restrict__ weq,
                const int* __restrict__ mask, float* __restrict__ outg,
                float* __restrict__ outh)
{
    extern __shared__ __align__(16) float smf[];
    uint32_t* smu = (uint32_t*)smf;
    const uint32_t sb = smem_u32(smf);
    const int tid = threadIdx.x, w = tid >> 5, lane = tid & 31;
    const int g = lane >> 2, t = lane & 3;
    const int loc = blockIdx.x;
    const int r8 = lane & 7, s01 = (lane >> 3) & 1, s2 = lane >> 4;
    // 2D roles for S/softmax/O
    const int wm = w >> 1, wn = w & 1;
    const int m0 = wm * 32;

    const float* g2l = g2 + (size_t)loc * 128 * 32;
    const float* h2l = h2 + (size_t)loc * 128 * 3;
    const float* swl = sw + (size_t)loc * 128;
    const int*   ml  = mask + (size_t)loc * 128;

    // ---- stage raw weights ----
    {
        const float4* s1 = (const float4*)wqk;
        float4* d1 = (float4*)(smf + F_RQK);
        #pragma unroll
        for (int i = 0; i < 8; ++i) d1[tid + i * 256] = s1[tid + i * 256];
        const float4* s2p = (const float4*)wv;
        float4* d2 = (float4*)(smf + F_RWV);
        #pragma unroll
        for (int i = 0; i < 4; ++i) d2[tid + i * 256] = s2p[tid + i * 256];
        const float4* s3 = (const float4*)wh;
        float4* d3 = (float4*)(smf + F_RWH);
        #pragma unroll
        for (int i = 0; i < 4; ++i) d3[tid + i * 256] = s3[tid + i * 256];
    }
    // ---- g2 -> bf16 hi/lo (thread = half row) ----
    {
        int r = tid >> 1, hf = tid & 1;
        const float* src = g2l + (size_t)r * 32 + hf * 16;
        float e[16];
        #pragma unroll
        for (int i = 0; i < 4; ++i) {
            float4 v = ((const float4*)src)[i];
            e[4*i] = v.x; e[4*i+1] = v.y; e[4*i+2] = v.z; e[4*i+3] = v.w;
        }
        #pragma unroll
        for (int j = 0; j < 8; ++j) {
            uint32_t hu, lu;
            pack_hl(e[2*j], e[2*j+1], hu, lu);
            smu[WG2H + r * 20 + hf * 8 + j] = hu;
            smu[WG2L + r * 20 + hf * 8 + j] = lu;
        }
    }
    if (tid < 128) {
        float a = h2l[tid * 3], b = h2l[tid * 3 + 1], c = h2l[tid * 3 + 2];
        float sv = swl[tid];
        ((float4*)(smf + F_H2SW4))[tid] = make_float4(a, b, c, ml[tid] ? sv : -sv);
    }
    if (tid < 32) smf[F_BH + tid] = bh[tid];
    if (tid < 4)  smf[F_WEQ + tid] = weq[tid];
    // zero Ct pad rows 35..39 (words 0..63)
    for (int i = tid; i < 320; i += THREADS) {
        int r = 35 + (i >> 6), wd = i & 63;
        smu[WCTH + r * 68 + wd] = 0;
        smu[WCTL + r * 68 + wd] = 0;
    }
    __syncthreads();

    // ---- WallT Q/K rows ----
    #pragma unroll 4
    for (int i = tid; i < 4096; i += THREADS) {
        int rqk = i >> 4, j = i & 15;
        int hh = rqk >> 6, r = rqk & 63;
        int c = hh * 96 + r;
        int src = (r < 32) ? r * 8 + hh : (r - 32) * 8 + 4 + hh;
        float v0 = smf[F_RQK + (2 * j) * 256 + src];
        float v1 = smf[F_RQK + (2 * j + 1) * 256 + src];
        uint32_t hu, lu;
        pack_hl(v0, v1, hu, lu);
        smu[WWTH + c * 20 + j] = hu;
        smu[WWTL + c * 20 + j] = lu;
    }
    // ---- WallT C rows: wc = wv @ wh folded per head ----
    if (tid < 128) {
        int hh = tid >> 5, m = tid & 31;
        float whcol[32];
        #pragma unroll 8
        for (int gg = 0; gg < 32; ++gg)
            whcol[gg] = smf[F_RWH + (gg * 4 + hh) * 32 + m];
        float acc[32];
        #pragma unroll 1
        for (int k = 0; k < 32; ++k) {
            const float* wvr = smf + F_RWV + k * 128 + hh;
            float s = 0.f;
            #pragma unroll
            for (int gg = 0; gg < 32; ++gg) s = fmaf(wvr[gg * 4], whcol[gg], s);
            acc[k] = s;
        }
        int c = hh * 96 + 64 + m;
        #pragma unroll
        for (int j = 0; j < 16; ++j) {
            uint32_t hu, lu;
            pack_hl(acc[2 * j], acc[2 * j + 1], hu, lu);
            smu[WWTH + c * 20 + j] = hu;
            smu[WWTL + c * 20 + j] = lu;
        }
    }
    __syncthreads();

    // ---- persistent state ----
    float oacc[2][5][4];
    #pragma unroll
    for (int a = 0; a < 2; ++a)
        #pragma unroll
        for (int b = 0; b < 5; ++b)
            #pragma unroll
            for (int c = 0; c < 4; ++c) oacc[a][b][c] = 0.f;
    float rswm[4], rh2I[4][3], rwL[4];
    #pragma unroll
    for (int j = 0; j < 4; ++j) {
        int row = m0 + (j >> 1) * 16 + (j & 1) * 8 + g;
        float4 rH = ((float4*)(smf + F_H2SW4))[row];
        rh2I[j][0] = rH.x * INV_SQRT_D;
        rh2I[j][1] = rH.y * INV_SQRT_D;
        rh2I[j][2] = rH.z * INV_SQRT_D;
        rwL[j] = fabsf(rH.w) * L2E;
        rswm[j] = fmaxf(rH.w, 0.f);
    }

    // lane-address bases (byte addrs)
    const int arowP = w * 16 + r8 + s01 * 8;
    const uint32_t aG2h = sb + 4 * (WG2H + arowP * 20 + s2 * 4);
    const uint32_t aG2l = sb + 4 * (WG2L + arowP * 20 + s2 * 4);
    const uint32_t stPH = sb + 4 * (WPHH + arowP * 36 + s2 * 4);
    const uint32_t stCT = sb + 4 * (WCTH + r8 * 68 + w * 8 + s01 * 4);
    const int arow0 = m0 + r8 + s01 * 8;
    const uint32_t aPH0 = sb + 4 * (WPHH + arow0 * 36 + s2 * 4);
    const uint32_t aPH1 = aPH0 + 4 * 16 * 36;
    const uint32_t aAP0 = sb + 4 * (WAPH + arow0 * 68 + wn * 32 + s2 * 4);
    const uint32_t aAP1 = aAP0 + 4 * 16 * 68;
    const float C50 = -50.0f * L2E;

    #pragma unroll 1
    for (int h = 0; h < 4; ++h) {
        // ======== GEMM_P (1D): Q(nt0-3)+K(nt4-7) -> Ph, C(nt8-11) -> Ct ========
        {
            float pacc[12][4];
            #pragma unroll
            for (int a = 0; a < 12; ++a)
                #pragma unroll
                for (int b = 0; b < 4; ++b) pacc[a][b] = 0.f;
            #pragma unroll
            for (int kk = 0; kk < 2; ++kk) {
                uint32_t ah[4], al[4];
                LDSM4(ah, aG2h + 32 * kk);
                LDSM4(al, aG2l + 32 * kk);
                #pragma unroll
                for (int ntp = 0; ntp < 6; ++ntp) {
                    int n = h * 96 + ntp * 16 + r8 + s2 * 8;
                    uint32_t bb = sb + 4 * (WWTH + n * 20 + kk * 8 + s01 * 4);
                    uint32_t bhr[4], blr[4];
                    LDSM4(bhr, bb);
                    LDSM4(blr, bb + 4 * (WWTL - WWTH));
                    mma3(pacc[2*ntp],   ah, al, bhr[0], bhr[1], blr[0], blr[1]);
                    mma3(pacc[2*ntp+1], ah, al, bhr[2], bhr[3], blr[2], blr[3]);
                }
            }
            #pragma unroll
            for (int ntp = 0; ntp < 4; ++ntp) {
                uint32_t h0, l0, h1, l1, h2r, l2, h3, l3;
                pack_hl(pacc[2*ntp][0],   pacc[2*ntp][1],   h0, l0);
                pack_hl(pacc[2*ntp][2],   pacc[2*ntp][3],   h1, l1);
                pack_hl(pacc[2*ntp+1][0], pacc[2*ntp+1][1], h2r, l2);
                pack_hl(pacc[2*ntp+1][2], pacc[2*ntp+1][3], h3, l3);
                STSM4(stPH + 32 * ntp, h0, h1, h2r, h3);
                STSM4(stPH + 32 * ntp + OFFPH, l0, l1, l2, l3);
            }
            #pragma unroll
            for (int nt = 8; nt < 12; ++nt) {
                int j0 = (nt - 8) * 8;
                uint32_t h0, l0, h1, l1;
                pack_hl(pacc[nt][0], pacc[nt][1], h0, l0);
                pack_hl(pacc[nt][2], pacc[nt][3], h1, l1);
                uint32_t ba = stCT + 4 * (j0 * 68);
                STSM2T(ba, h0, h1);
                STSM2T(ba + OFFCT, l0, l1);
            }
        }
        // Ct rows 32..34: h2[k][c] * weq_h (bf16 hi/lo), k-pairs by tid<64
        if (tid < 64) {
            float wqh = smf[F_WEQ + h];
            float4 ha = ((float4*)(smf + F_H2SW4))[2 * tid];
            float4 hb = ((float4*)(smf + F_H2SW4))[2 * tid + 1];
            uint32_t hu, lu;
            pack_hl(ha.x * wqh, hb.x * wqh, hu, lu);
            smu[WCTH + 32 * 68 + tid] = hu; smu[WCTL + 32 * 68 + tid] = lu;
            pack_hl(ha.y * wqh, hb.y * wqh, hu, lu);
            smu[WCTH + 33 * 68 + tid] = hu; smu[WCTL + 33 * 68 + tid] = lu;
            pack_hl(ha.z * wqh, hb.z * wqh, hu, lu);
            smu[WCTH + 34 * 68 + tid] = hu; smu[WCTL + 34 * 68 + tid] = lu;
        }
        __syncthreads();

        // ======== GEMM_S (2D): rows m0..m0+31, cols wn*64..+63 ========
        float sacc[2][8][4];
        #pragma unroll
        for (int a = 0; a < 2; ++a)
            #pragma unroll
            for (int b = 0; b < 8; ++b)
                #pragma unroll
                for (int c = 0; c < 4; ++c) sacc[a][b][c] = 0.f;
        #pragma unroll
        for (int kk = 0; kk < 2; ++kk) {
            uint32_t ah0[4], al0[4], ah1[4], al1[4];
            LDSM4(ah0, aPH0 + 32 * kk);
            LDSM4(al0, aPH0 + 32 * kk + OFFPH);
            LDSM4(ah1, aPH1 + 32 * kk);
            LDSM4(al1, aPH1 + 32 * kk + OFFPH);
            #pragma unroll
            for (int ntp = 0; ntp < 4; ++ntp) {
                int n = wn * 64 + ntp * 16 + r8 + s2 * 8;
                uint32_t bb = sb + 4 * (WPHH + n * 36 + 16 + kk * 8 + s01 * 4);
                uint32_t bhr[4], blr[4];
                LDSM4(bhr, bb);
                LDSM4(blr, bb + OFFPH);
                mma3(sacc[0][2*ntp],   ah0, al0, bhr[0], bhr[1], blr[0], blr[1]);
                mma3(sacc[0][2*ntp+1], ah0, al0, bhr[2], bhr[3], blr[2], blr[3]);
                mma3(sacc[1][2*ntp],   ah1, al1, bhr[0], bhr[1], blr[0], blr[1]);
                mma3(sacc[1][2*ntp+1], ah1, al1, bhr[2], bhr[3], blr[2], blr[3]);
            }
        }

        // ======== softmax pass: e + partial sums over warp's 64 cols ========
        float ssum[4] = {0.f, 0.f, 0.f, 0.f};
        #pragma unroll
        for (int nt = 0; nt < 8; ++nt) {
            #pragma unroll
            for (int b = 0; b < 2; ++b) {
                int col = wn * 64 + nt * 8 + 2 * t + b;
                float4 hc = ((float4*)(smf + F_H2SW4))[col];
                float cw = fabsf(hc.w), cm = fmaxf(hc.w, 0.f);
                #pragma unroll
                for (int f = 0; f < 2; ++f)
                    #pragma unroll
                    for (int d = 0; d < 2; ++d) {
                        int j = f * 2 + d;
                        float dot = sacc[f][nt][d * 2 + b];
                        float h2dI = fmaf(rh2I[j][0], hc.x,
                                   fmaf(rh2I[j][1], hc.y, rh2I[j][2] * hc.z));
                        float t1 = fmaf(dot, h2dI, ATTNW_SHIFT);
                        float e = ex2a(fmaf(t1, cw * rwL[j], C50));
                        ssum[j] += e;
                        sacc[f][nt][d * 2 + b] = (e * cm) * h2dI;
                    }
            }
        }
        #pragma unroll
        for (int j = 0; j < 4; ++j) {
            float s = ssum[j];
            s += __shfl_xor_sync(0xffffffffu, s, 1);
            s += __shfl_xor_sync(0xffffffffu, s, 2);
            if (t == 0) {
                int row = m0 + (j >> 1) * 16 + (j & 1) * 8 + g;
                smf[F_PART + row * 2 + wn] = s;
            }
        }
        __syncthreads();
        float rs[4];
        #pragma unroll
        for (int j = 0; j < 4; ++j) {
            int row = m0 + (j >> 1) * 16 + (j & 1) * 8 + g;
            float2 p = *(float2*)(smf + F_PART + row * 2);
            rs[j] = rswm[j] * SQRT32 / (fmaxf(p.x + p.y, 1e-30f) * SQRT3);
        }
        // A' -> smem (hi/lo), warp-private rows+cols
        #pragma unroll
        for (int f = 0; f < 2; ++f) {
            uint32_t stA = (f ? aAP1 : aAP0);
            #pragma unroll
            for (int ntp = 0; ntp < 4; ++ntp) {
                uint32_t h0, l0, h1, l1, h2r, l2, h3, l3;
                pack_hl(sacc[f][2*ntp][0]   * rs[f*2],   sacc[f][2*ntp][1]   * rs[f*2],   h0, l0);
                pack_hl(sacc[f][2*ntp][2]   * rs[f*2+1], sacc[f][2*ntp][3]   * rs[f*2+1], h1, l1);
                pack_hl(sacc[f][2*ntp+1][0] * rs[f*2],   sacc[f][2*ntp+1][1] * rs[f*2],   h2r, l2);
                pack_hl(sacc[f][2*ntp+1][2] * rs[f*2+1], sacc[f][2*ntp+1][3] * rs[f*2+1], h3, l3);
                STSM4(stA + 32 * ntp, h0, h1, h2r, h3);
                STSM4(stA + 32 * ntp + OFFAP, l0, l1, l2, l3);
            }
        }
        __syncwarp();

        // ======== GEMM_O (2D partial over k-slice): cols 0..31 + h2 cols ========
        #pragma unroll
        for (int kk = 0; kk < 4; ++kk) {
            uint32_t ah0[4], al0[4], ah1[4], al1[4];
            LDSM4(ah0, aAP0 + 32 * kk);
            LDSM4(al0, aAP0 + 32 * kk + OFFAP);
            LDSM4(ah1, aAP1 + 32 * kk);
            LDSM4(al1, aAP1 + 32 * kk + OFFAP);
            #pragma unroll
            for (int ntp = 0; ntp < 2; ++ntp) {
                int n = ntp * 16 + r8 + s2 * 8;
                uint32_t bb = sb + 4 * (WCTH + n * 68 + wn * 32 + kk * 8 + s01 * 4);
                uint32_t bhr[4], blr[4];
                LDSM4(bhr, bb);
                LDSM4(blr, bb + OFFCT);
                mma3(oacc[0][2*ntp],   ah0, al0, bhr[0], bhr[1], blr[0], blr[1]);
                mma3(oacc[0][2*ntp+1], ah0, al0, bhr[2], bhr[3], blr[2], blr[3]);
                mma3(oacc[1][2*ntp],   ah1, al1, bhr[0], bhr[1], blr[0], blr[1]);
                mma3(oacc[1][2*ntp+1], ah1, al1, bhr[2], bhr[3], blr[2], blr[3]);
            }
            {   // extra n8 group: rows 32..39 (h2*weq cols, rows 35-39 zero)
                uint32_t bb2 = sb + 4 * (WCTH + (32 + r8) * 68 + wn * 32 + kk * 8 + s01 * 4);
                uint32_t b2h[2], b2l[2];
                LDSM2(b2h, bb2);
                LDSM2(b2l, bb2 + OFFCT);
                mma3(oacc[0][4], ah0, al0, b2h[0], b2h[1], b2l[0], b2l[1]);
                mma3(oacc[1][4], ah1, al1, b2h[0], b2h[1], b2l[0], b2l[1]);
            }
        }
        __syncthreads();   // Ph/Ct reused next head
    }

    // ---- final cross-wn reduction + outputs ----
    if (wn == 1) {
        #pragma unroll
        for (int f = 0; f < 2; ++f)
            #pragma unroll
            for (int d = 0; d < 2; ++d) {
                int row = m0 + f * 16 + d * 8 + g;
                #pragma unroll
                for (int grp = 0; grp < 5; ++grp)
                    *(float2*)(smf + RBUF + row * 40 + grp * 8 + 2 * t) =
                        make_float2(oacc[f][grp][d * 2], oacc[f][grp][d * 2 + 1]);
            }
    }
    __syncthreads();
    if (wn == 0) {
        #pragma unroll
        for (int f = 0; f < 2; ++f)
            #pragma unroll
            for (int d = 0; d < 2; ++d) {
                int row = m0 + f * 16 + d * 8 + g;
                float* go = outg + ((size_t)loc * 128 + row) * 32;
                #pragma unroll
                for (int grp = 0; grp < 4; ++grp) {
                    int col = grp * 8 + 2 * t;
                    float2 r = *(float2*)(smf + RBUF + row * 40 + grp * 8 + 2 * t);
                    float2 v = make_float2(oacc[f][grp][d*2]   + r.x + smf[F_BH + col],
                                           oacc[f][grp][d*2+1] + r.y + smf[F_BH + col + 1]);
                    *(float2*)(go + col) = v;
                }
                if (outh) {
                    float2 r4 = *(float2*)(smf + RBUF + row * 40 + 32 + 2 * t);
                    float v0 = oacc[f][4][d*2] + r4.x;
                    float v1 = oacc[f][4][d*2+1] + r4.y;
                    float* ho = outh + ((size_t)loc * 128 + row) * 3;
                    if (t == 0) { ho[0] = v0; ho[1] = v1; }
                    else if (t == 1) { ho[2] = v0; }
                }
            }
    }
}

extern "C" void kernel_launch(void* const* d_in, const int* in_sizes, int n_in,
                              void* d_out, int out_size) {
    const float* g2  = (const float*)d_in[0];
    const float* h2  = (const float*)d_in[1];
    const float* sw  = (const float*)d_in[2];
    const float* wqk = (const float*)d_in[3];
    const float* wv  = (const float*)d_in[4];
    const float* wh  = (const float*)d_in[5];
    const float* bh  = (const float*)d_in[6];
    const float* weq = (const float*)d_in[7];
    const int*   msk = (const int*)d_in[8];

    int nloc = in_sizes[2] / 128;
    float* outg = (float*)d_out;
    size_t gsz = (size_t)nloc * 128 * 32;
    float* outh = ((size_t)out_size >= gsz + (size_t)nloc * 128 * 3) ? outg + gsz : nullptr;

    cudaFuncSetAttribute(rep_bf16_kernel, cudaFuncAttributeMaxDynamicSharedMemorySize, SMEM_BYTES);
    rep_bf16_kernel<<<nloc, THREADS, SMEM_BYTES>>>(g2, h2, sw, wqk, wv, wh, bh, weq, msk, outg, outh);
}

// round 15
// speedup vs baseline: 1.3606x; 1.1008x over previous
#include <cuda_runtime.h>
#include <cuda_bf16.h>
#include <cstdint>

#define THREADS 512
#define ATTNW_SHIFT 20.0f
#define INV_SQRT_D  0.17677669529663687f
#define SQRT3       1.7320508075688772f
#define SQRT32      5.656854249492381f
#define L2E         1.4426950408889634f

// word(=float)-index smem layout
#define WG2H  0        // 128*20
#define WG2L  2560
#define WWTH  5120     // 384*20 (reused as RBUF after head loop)
#define WWTL  12800
#define WPHH  20480    // 128*36 (Q words 0-15, K words 16-31)
#define WPHL  25088
#define WCTH  29696    // 40*68 (rows 0-31 C^T, 32-34 h2*weq, 35-39 zero)
#define WCTL  32416
#define F_H2SW4 35136  // float4[128]: (h2x,h2y,h2z, mask? sw : -sw)
#define F_BH   35648
#define F_WEQ  35680
#define F_PART 35712   // 128*2 row-sum partials
#define F_RQK  35968   // init-only scratch
#define F_RWV  44160
#define F_RWH  48256
#define SMEM_BYTES 209408
#define RBUF  WWTH
#define OFFPH 18432    // bytes WPHL-WPHH
#define OFFCT 10880    // bytes WCTL-WCTH

static __device__ __forceinline__ uint32_t smem_u32(const void* p) {
    uint32_t a;
    asm("{ .reg .u64 t; cvta.to.shared.u64 t, %1; cvt.u32.u64 %0, t; }" : "=r"(a) : "l"(p));
    return a;
}
static __device__ __forceinline__ uint32_t packb(float e0, float e1) {
    uint32_t r;
    asm("cvt.rn.bf16x2.f32 %0, %1, %2;" : "=r"(r) : "f"(e1), "f"(e0));
    return r;
}
static __device__ __forceinline__ void pack_hl(float v0, float v1,
                                               uint32_t& h, uint32_t& l) {
    h = packb(v0, v1);
    float h0 = __uint_as_float(h << 16);
    float h1 = __uint_as_float(h & 0xFFFF0000u);
    l = packb(v0 - h0, v1 - h1);
}
static __device__ __forceinline__ float ex2a(float x) {
    float r; asm("ex2.approx.f32 %0, %1;" : "=f"(r) : "f"(x)); return r;
}
static __device__ __forceinline__ void mma16(float* d, uint32_t a0, uint32_t a1,
                                             uint32_t a2, uint32_t a3,
                                             uint32_t b0, uint32_t b1) {
    asm volatile("mma.sync.aligned.m16n8k16.row.col.f32.bf16.bf16.f32 "
                 "{%0,%1,%2,%3}, {%4,%5,%6,%7}, {%8,%9}, {%0,%1,%2,%3};"
                 : "+f"(d[0]), "+f"(d[1]), "+f"(d[2]), "+f"(d[3])
                 : "r"(a0), "r"(a1), "r"(a2), "r"(a3), "r"(b0), "r"(b1));
}
static __device__ __forceinline__ void mma3(float* d, const uint32_t* ah,
                                            const uint32_t* al,
                                            uint32_t bh0, uint32_t bh1,
                                            uint32_t bl0, uint32_t bl1) {
    mma16(d, ah[0], ah[1], ah[2], ah[3], bh0, bh1);
    mma16(d, al[0], al[1], al[2], al[3], bh0, bh1);
    mma16(d, ah[0], ah[1], ah[2], ah[3], bl0, bl1);
}
static __device__ __forceinline__ void afrag_from_acc(const float* acc0, const float* acc1,
                                                      float s0, float s1,
                                                      uint32_t* ah, uint32_t* al) {
    pack_hl(acc0[0] * s0, acc0[1] * s0, ah[0], al[0]);
    pack_hl(acc0[2] * s1, acc0[3] * s1, ah[1], al[1]);
    pack_hl(acc1[0] * s0, acc1[1] * s0, ah[2], al[2]);
    pack_hl(acc1[2] * s1, acc1[3] * s1, ah[3], al[3]);
}
#define LDSM4(r, ba) \
    asm volatile("ldmatrix.sync.aligned.m8n8.x4.shared.b16 {%0,%1,%2,%3}, [%4];" \
                 : "=r"((r)[0]), "=r"((r)[1]), "=r"((r)[2]), "=r"((r)[3]) : "r"(ba))
#define LDSM2(r, ba) \
    asm volatile("ldmatrix.sync.aligned.m8n8.x2.shared.b16 {%0,%1}, [%2];" \
                 : "=r"((r)[0]), "=r"((r)[1]) : "r"(ba))
#define STSM4(ba, r0, r1, r2, r3) \
    asm volatile("stmatrix.sync.aligned.m8n8.x4.shared.b16 [%0], {%1,%2,%3,%4};" \
                 :: "r"(ba), "r"(r0), "r"(r1), "r"(r2), "r"(r3))
#define STSM2T(ba, r0, r1) \
    asm volatile("stmatrix.sync.aligned.m8n8.x2.trans.shared.b16 [%0], {%1,%2};" \
                 :: "r"(ba), "r"(r0), "r"(r1))

__global__ void __launch_bounds__(THREADS, 1)
rep_bf16_kernel(const float* __restrict__ g2, const float* __restrict__ h2,
                const float* __restrict__ sw, const float* __restrict__ wqk,
                const float* __restrict__ wv, const float* __restrict__ wh,
                const float* __restrict__ bh, const float* __restrict__ weq,
                const int* __restrict__ mask, float* __restrict__ outg,
                float* __restrict__ outh)
{
    extern __shared__ __align__(16) float smf[];
    uint32_t* smu = (uint32_t*)smf;
    const uint32_t sb = smem_u32(smf);
    const int tid = threadIdx.x, w = tid >> 5, lane = tid & 31;
    const int g = lane >> 2, t = lane & 3;
    const int loc = blockIdx.x;
    const int r8 = lane & 7, s01 = (lane >> 3) & 1, s2 = lane >> 4;
    // 8x2 warp grid
    const int wm = w >> 1, wn = w & 1;
    const int m0 = wm * 16;

    const float* g2l = g2 + (size_t)loc * 128 * 32;
    const float* h2l = h2 + (size_t)loc * 128 * 3;
    const float* swl = sw + (size_t)loc * 128;
    const int*   ml  = mask + (size_t)loc * 128;

    // ---- stage raw weights ----
    {
        const float4* s1 = (const float4*)wqk;
        float4* d1 = (float4*)(smf + F_RQK);
        #pragma unroll
        for (int i = 0; i < 4; ++i) d1[tid + i * 512] = s1[tid + i * 512];
        const float4* s2p = (const float4*)wv;
        float4* d2 = (float4*)(smf + F_RWV);
        #pragma unroll
        for (int i = 0; i < 2; ++i) d2[tid + i * 512] = s2p[tid + i * 512];
        const float4* s3 = (const float4*)wh;
        float4* d3 = (float4*)(smf + F_RWH);
        #pragma unroll
        for (int i = 0; i < 2; ++i) d3[tid + i * 512] = s3[tid + i * 512];
    }
    // ---- g2 -> bf16 hi/lo (threads 0-255, thread = half row) ----
    if (tid < 256) {
        int r = tid >> 1, hf = tid & 1;
        const float* src = g2l + (size_t)r * 32 + hf * 16;
        float e[16];
        #pragma unroll
        for (int i = 0; i < 4; ++i) {
            float4 v = ((const float4*)src)[i];
            e[4*i] = v.x; e[4*i+1] = v.y; e[4*i+2] = v.z; e[4*i+3] = v.w;
        }
        #pragma unroll
        for (int j = 0; j < 8; ++j) {
            uint32_t hu, lu;
            pack_hl(e[2*j], e[2*j+1], hu, lu);
            smu[WG2H + r * 20 + hf * 8 + j] = hu;
            smu[WG2L + r * 20 + hf * 8 + j] = lu;
        }
    }
    if (tid < 128) {
        float a = h2l[tid * 3], b = h2l[tid * 3 + 1], c = h2l[tid * 3 + 2];
        float sv = swl[tid];
        ((float4*)(smf + F_H2SW4))[tid] = make_float4(a, b, c, ml[tid] ? sv : -sv);
    }
    if (tid < 32) smf[F_BH + tid] = bh[tid];
    if (tid < 4)  smf[F_WEQ + tid] = weq[tid];
    // zero Ct pad rows 35..39
    for (int i = tid; i < 320; i += THREADS) {
        int r = 35 + (i >> 6), wd = i & 63;
        smu[WCTH + r * 68 + wd] = 0;
        smu[WCTL + r * 68 + wd] = 0;
    }
    __syncthreads();

    // ---- WallT Q/K rows ----
    #pragma unroll 2
    for (int i = tid; i < 4096; i += THREADS) {
        int rqk = i >> 4, j = i & 15;
        int hh = rqk >> 6, r = rqk & 63;
        int c = hh * 96 + r;
        int src = (r < 32) ? r * 8 + hh : (r - 32) * 8 + 4 + hh;
        float v0 = smf[F_RQK + (2 * j) * 256 + src];
        float v1 = smf[F_RQK + (2 * j + 1) * 256 + src];
        uint32_t hu, lu;
        pack_hl(v0, v1, hu, lu);
        smu[WWTH + c * 20 + j] = hu;
        smu[WWTL + c * 20 + j] = lu;
    }
    // ---- WallT C rows: wc = wv @ wh folded per head ----
    if (tid < 128) {
        int hh = tid >> 5, m = tid & 31;
        float whcol[32];
        #pragma unroll 8
        for (int gg = 0; gg < 32; ++gg)
            whcol[gg] = smf[F_RWH + (gg * 4 + hh) * 32 + m];
        float acc[32];
        #pragma unroll 1
        for (int k = 0; k < 32; ++k) {
            const float* wvr = smf + F_RWV + k * 128 + hh;
            float s = 0.f;
            #pragma unroll
            for (int gg = 0; gg < 32; ++gg) s = fmaf(wvr[gg * 4], whcol[gg], s);
            acc[k] = s;
        }
        int c = hh * 96 + 64 + m;
        #pragma unroll
        for (int j = 0; j < 16; ++j) {
            uint32_t hu, lu;
            pack_hl(acc[2 * j], acc[2 * j + 1], hu, lu);
            smu[WWTH + c * 20 + j] = hu;
            smu[WWTL + c * 20 + j] = lu;
        }
    }
    __syncthreads();

    // ---- persistent state (warp owns 16 rows m0..m0+15; lane rows g, 8+g) ----
    float oacc[5][4];
    #pragma unroll
    for (int a = 0; a < 5; ++a)
        #pragma unroll
        for (int b = 0; b < 4; ++b) oacc[a][b] = 0.f;
    float rswm[2], rh2I[2][3], rwL[2];
    #pragma unroll
    for (int d = 0; d < 2; ++d) {
        int row = m0 + d * 8 + g;
        float4 rH = ((float4*)(smf + F_H2SW4))[row];
        rh2I[d][0] = rH.x * INV_SQRT_D;
        rh2I[d][1] = rH.y * INV_SQRT_D;
        rh2I[d][2] = rH.z * INV_SQRT_D;
        rwL[d] = fabsf(rH.w) * L2E;
        rswm[d] = fmaxf(rH.w, 0.f);
    }

    // lane-address bases (byte addrs)
    const int arow = m0 + r8 + s01 * 8;
    const uint32_t aG2h = sb + 4 * (WG2H + arow * 20 + s2 * 4);
    const uint32_t aG2l = sb + 4 * (WG2L + arow * 20 + s2 * 4);
    const uint32_t aPHh = sb + 4 * (WPHH + arow * 36 + s2 * 4);
    const uint32_t stPH = aPHh;
    const uint32_t stCT = sb + 4 * (WCTH + r8 * 68 + wm * 8 + s01 * 4);
    const float C50 = -50.0f * L2E;

    #pragma unroll 1
    for (int h = 0; h < 4; ++h) {
        // ======== GEMM_P (2D): rows m0..+15, cols h*96 + wn*48 .. +47 ========
        {
            float pacc[6][4];
            #pragma unroll
            for (int a = 0; a < 6; ++a)
                #pragma unroll
                for (int b = 0; b < 4; ++b) pacc[a][b] = 0.f;
            #pragma unroll
            for (int kk = 0; kk < 2; ++kk) {
                uint32_t ah[4], al[4];
                LDSM4(ah, aG2h + 32 * kk);
                LDSM4(al, aG2l + 32 * kk);
                #pragma unroll
                for (int ntp = 0; ntp < 3; ++ntp) {
                    int n = h * 96 + wn * 48 + ntp * 16 + r8 + s2 * 8;
                    uint32_t bb = sb + 4 * (WWTH + n * 20 + kk * 8 + s01 * 4);
                    uint32_t bhr[4], blr[4];
                    LDSM4(bhr, bb);
                    LDSM4(blr, bb + 4 * (WWTL - WWTH));
                    mma3(pacc[2*ntp],   ah, al, bhr[0], bhr[1], blr[0], blr[1]);
                    mma3(pacc[2*ntp+1], ah, al, bhr[2], bhr[3], blr[2], blr[3]);
                }
            }
            if (wn == 0) {
                // cols 0..47 = Q(0..31) + K(0..15) -> Ph words {0-7,8-15,16-23}
                #pragma unroll
                for (int ntp = 0; ntp < 3; ++ntp) {
                    uint32_t h0, l0, h1, l1, h2r, l2, h3, l3;
                    pack_hl(pacc[2*ntp][0],   pacc[2*ntp][1],   h0, l0);
                    pack_hl(pacc[2*ntp][2],   pacc[2*ntp][3],   h1, l1);
                    pack_hl(pacc[2*ntp+1][0], pacc[2*ntp+1][1], h2r, l2);
                    pack_hl(pacc[2*ntp+1][2], pacc[2*ntp+1][3], h3, l3);
                    STSM4(stPH + 32 * ntp, h0, h1, h2r, h3);
                    STSM4(stPH + 32 * ntp + OFFPH, l0, l1, l2, l3);
                }
            } else {
                // pair 0: cols 48..63 = K(16..31) -> Ph words 24..31
                {
                    uint32_t h0, l0, h1, l1, h2r, l2, h3, l3;
                    pack_hl(pacc[0][0], pacc[0][1], h0, l0);
                    pack_hl(pacc[0][2], pacc[0][3], h1, l1);
                    pack_hl(pacc[1][0], pacc[1][1], h2r, l2);
                    pack_hl(pacc[1][2], pacc[1][3], h3, l3);
                    STSM4(stPH + 96, h0, h1, h2r, h3);
                    STSM4(stPH + 96 + OFFPH, l0, l1, l2, l3);
                }
                // groups 2..5: C cols 0..31 -> Ct transposed (k slice wm*16)
                #pragma unroll
                for (int grp = 2; grp < 6; ++grp) {
                    int j0 = (grp - 2) * 8;
                    uint32_t h0, l0, h1, l1;
                    pack_hl(pacc[grp][0], pacc[grp][1], h0, l0);
                    pack_hl(pacc[grp][2], pacc[grp][3], h1, l1);
                    uint32_t ba = stCT + 4 * (j0 * 68);
                    STSM2T(ba, h0, h1);
                    STSM2T(ba + OFFCT, l0, l1);
                }
            }
        }
        // Ct rows 32..34: h2[k][c] * weq_h
        if (tid < 64) {
            float wqh = smf[F_WEQ + h];
            float4 ha = ((float4*)(smf + F_H2SW4))[2 * tid];
            float4 hb = ((float4*)(smf + F_H2SW4))[2 * tid + 1];
            uint32_t hu, lu;
            pack_hl(ha.x * wqh, hb.x * wqh, hu, lu);
            smu[WCTH + 32 * 68 + tid] = hu; smu[WCTL + 32 * 68 + tid] = lu;
            pack_hl(ha.y * wqh, hb.y * wqh, hu, lu);
            smu[WCTH + 33 * 68 + tid] = hu; smu[WCTL + 33 * 68 + tid] = lu;
            pack_hl(ha.z * wqh, hb.z * wqh, hu, lu);
            smu[WCTH + 34 * 68 + tid] = hu; smu[WCTL + 34 * 68 + tid] = lu;
        }
        __syncthreads();

        // ======== GEMM_S (2D): rows m0..+15, cols wn*64..+63 ========
        float sacc[8][4];
        #pragma unroll
        for (int a = 0; a < 8; ++a)
            #pragma unroll
            for (int b = 0; b < 4; ++b) sacc[a][b] = 0.f;
        #pragma unroll
        for (int kk = 0; kk < 2; ++kk) {
            uint32_t ah[4], al[4];
            LDSM4(ah, aPHh + 32 * kk);
            LDSM4(al, aPHh + 32 * kk + OFFPH);
            #pragma unroll
            for (int ntp = 0; ntp < 4; ++ntp) {
                int n = wn * 64 + ntp * 16 + r8 + s2 * 8;
                uint32_t bb = sb + 4 * (WPHH + n * 36 + 16 + kk * 8 + s01 * 4);
                uint32_t bhr[4], blr[4];
                LDSM4(bhr, bb);
                LDSM4(blr, bb + OFFPH);
                mma3(sacc[2*ntp],   ah, al, bhr[0], bhr[1], blr[0], blr[1]);
                mma3(sacc[2*ntp+1], ah, al, bhr[2], bhr[3], blr[2], blr[3]);
            }
        }

        // ======== softmax: e + partial sums over warp's 64 cols ========
        float ssum[2] = {0.f, 0.f};
        #pragma unroll
        for (int nt = 0; nt < 8; ++nt) {
            #pragma unroll
            for (int b = 0; b < 2; ++b) {
                int col = wn * 64 + nt * 8 + 2 * t + b;
                float4 hc = ((float4*)(smf + F_H2SW4))[col];
                float cw = fabsf(hc.w), cm = fmaxf(hc.w, 0.f);
                #pragma unroll
                for (int d = 0; d < 2; ++d) {
                    float dot = sacc[nt][d * 2 + b];
                    float h2dI = fmaf(rh2I[d][0], hc.x,
                               fmaf(rh2I[d][1], hc.y, rh2I[d][2] * hc.z));
                    float t1 = fmaf(dot, h2dI, ATTNW_SHIFT);
                    float e = ex2a(fmaf(t1, cw * rwL[d], C50));
                    ssum[d] += e;
                    sacc[nt][d * 2 + b] = (e * cm) * h2dI;
                }
            }
        }
        #pragma unroll
        for (int d = 0; d < 2; ++d) {
            float s = ssum[d];
            s += __shfl_xor_sync(0xffffffffu, s, 1);
            s += __shfl_xor_sync(0xffffffffu, s, 2);
            if (t == 0)
                smf[F_PART + (m0 + d * 8 + g) * 2 + wn] = s;
        }
        __syncthreads();
        float rs[2];
        #pragma unroll
        for (int d = 0; d < 2; ++d) {
            float2 p = *(float2*)(smf + F_PART + (m0 + d * 8 + g) * 2);
            rs[d] = rswm[d] * SQRT32 / (fmaxf(p.x + p.y, 1e-30f) * SQRT3);
        }

        // ======== GEMM_O: A = A' from sacc registers; B = Ct (k-slice wn*64) ========
        #pragma unroll
        for (int kk = 0; kk < 4; ++kk) {
            uint32_t ah[4], al[4];
            afrag_from_acc(sacc[2*kk], sacc[2*kk+1], rs[0], rs[1], ah, al);
            #pragma unroll
            for (int ntp = 0; ntp < 2; ++ntp) {
                int n = ntp * 16 + r8 + s2 * 8;
                uint32_t bb = sb + 4 * (WCTH + n * 68 + wn * 32 + kk * 8 + s01 * 4);
                uint32_t bhr[4], blr[4];
                LDSM4(bhr, bb);
                LDSM4(blr, bb + OFFCT);
                mma3(oacc[2*ntp],   ah, al, bhr[0], bhr[1], blr[0], blr[1]);
                mma3(oacc[2*ntp+1], ah, al, bhr[2], bhr[3], blr[2], blr[3]);
            }
            {   // rows 32..39 of Ct: h2*weq cols (35-39 zero)
                uint32_t bb2 = sb + 4 * (WCTH + (32 + r8) * 68 + wn * 32 + kk * 8 + s01 * 4);
                uint32_t b2h[2], b2l[2];
                LDSM2(b2h, bb2);
                LDSM2(b2l, bb2 + OFFCT);
                mma3(oacc[4], ah, al, b2h[0], b2h[1], b2l[0], b2l[1]);
            }
        }
        __syncthreads();   // Ph/Ct reused next head
    }

    // ---- cross-wn reduction + outputs ----
    if (wn == 1) {
        #pragma unroll
        for (int d = 0; d < 2; ++d) {
            int row = m0 + d * 8 + g;
            #pragma unroll
            for (int grp = 0; grp < 5; ++grp)
                *(float2*)(smf + RBUF + row * 40 + grp * 8 + 2 * t) =
                    make_float2(oacc[grp][d * 2], oacc[grp][d * 2 + 1]);
        }
    }
    __syncthreads();
    if (wn == 0) {
        #pragma unroll
        for (int d = 0; d < 2; ++d) {
            int row = m0 + d * 8 + g;
            float* go = outg + ((size_t)loc * 128 + row) * 32;
            #pragma unroll
            for (int grp = 0; grp < 4; ++grp) {
                int col = grp * 8 + 2 * t;
                float2 r = *(float2*)(smf + RBUF + row * 40 + grp * 8 + 2 * t);
                float2 v = make_float2(oacc[grp][d*2]   + r.x + smf[F_BH + col],
                                       oacc[grp][d*2+1] + r.y + smf[F_BH + col + 1]);
                *(float2*)(go + col) = v;
            }
            if (outh) {
                float2 r4 = *(float2*)(smf + RBUF + row * 40 + 32 + 2 * t);
                float v0 = oacc[4][d*2] + r4.x;
                float v1 = oacc[4][d*2+1] + r4.y;
                float* ho = outh + ((size_t)loc * 128 + row) * 3;
                if (t == 0) { ho[0] = v0; ho[1] = v1; }
                else if (t == 1) { ho[2] = v0; }
            }
        }
    }
}

extern "C" void kernel_launch(void* const* d_in, const int* in_sizes, int n_in,
                              void* d_out, int out_size) {
    const float* g2  = (const float*)d_in[0];
    const float* h2  = (const float*)d_in[1];
    const float* sw  = (const float*)d_in[2];
    const float* wqk = (const float*)d_in[3];
    const float* wv  = (const float*)d_in[4];
    const float* wh  = (const float*)d_in[5];
    const float* bh  = (const float*)d_in[6];
    const float* weq = (const float*)d_in[7];
    const int*   msk = (const int*)d_in[8];

    int nloc = in_sizes[2] / 128;
    float* outg = (float*)d_out;
    size_t gsz = (size_t)nloc * 128 * 32;
    float* outh = ((size_t)out_size >= gsz + (size_t)nloc * 128 * 3) ? outg + gsz : nullptr;

    cudaFuncSetAttribute(rep_bf16_kernel, cudaFuncAttributeMaxDynamicSharedMemorySize, SMEM_BYTES);
    rep_bf16_kernel<<<nloc, THREADS, SMEM_BYTES>>>(g2, h2, sw, wqk, wv, wh, bh, weq, msk, outg, outh);
}